// round 14
// baseline (speedup 1.0000x reference)
#include <cuda_runtime.h>
#include <cuda_bf16.h>
#include <math.h>
#include <stdint.h>

// ---------------------------------------------------------------------------
// Problem dims
// ---------------------------------------------------------------------------
#define NB 256
#define ND 512
#define NL 64
#define NH 300
#define NHP 320                   // H padded to 5 * 64
#define MTOT (NB * ND)            // 131072 decoder rows (m = b*512 + d)

// ---------------------------------------------------------------------------
// Scratch (__device__ globals — no cudaMalloc allowed), 16B-aligned
// ---------------------------------------------------------------------------
__device__ __align__(16) __nv_bfloat16 g_g1w_hi[NHP * NL];
__device__ __align__(16) __nv_bfloat16 g_g1w_lo[NHP * NL];
__device__ __align__(16) __nv_bfloat16 g_g2w_hi[NHP * NHP];
__device__ __align__(16) __nv_bfloat16 g_g2w_lo[NHP * NHP];

// ---------------------------------------------------------------------------
// mma.sync / ldmatrix / cp.async helpers (baseline PTX, legal on sm_103)
// ---------------------------------------------------------------------------
__device__ __forceinline__ uint32_t smem_u32(const void* p) {
    uint32_t a;
    asm("{ .reg .u64 t; cvta.to.shared.u64 t, %1; cvt.u32.u64 %0, t; }"
        : "=r"(a) : "l"(p));
    return a;
}

__device__ __forceinline__ void mma16816(float* c, const uint32_t* a,
                                         uint32_t b0, uint32_t b1) {
    asm volatile(
        "mma.sync.aligned.m16n8k16.row.col.f32.bf16.bf16.f32 "
        "{%0,%1,%2,%3}, {%4,%5,%6,%7}, {%8,%9}, {%0,%1,%2,%3};"
        : "+f"(c[0]), "+f"(c[1]), "+f"(c[2]), "+f"(c[3])
        : "r"(a[0]), "r"(a[1]), "r"(a[2]), "r"(a[3]), "r"(b0), "r"(b1));
}

__device__ __forceinline__ void ldsm_x4(uint32_t* r, uint32_t addr) {
    asm volatile("ldmatrix.sync.aligned.m8n8.x4.shared.b16 {%0,%1,%2,%3}, [%4];"
                 : "=r"(r[0]), "=r"(r[1]), "=r"(r[2]), "=r"(r[3]) : "r"(addr));
}

__device__ __forceinline__ void cpasync16(uint32_t saddr, const void* gptr) {
    asm volatile("cp.async.cg.shared.global [%0], [%1], 16;"
                 :: "r"(saddr), "l"(gptr) : "memory");
}
#define CP_COMMIT() asm volatile("cp.async.commit_group;" ::: "memory")
#define CP_WAIT(n)  asm volatile("cp.async.wait_group %0;" :: "n"(n) : "memory")

__device__ __forceinline__ uint32_t pack2bf(float a, float b) {
    __nv_bfloat162 t = __floats2bfloat162_rn(a, b);
    return *reinterpret_cast<uint32_t*>(&t);
}

__device__ __forceinline__ void split_bf(float v, float& hi, float& lo) {
    __nv_bfloat16 h = __float2bfloat16(v);
    hi = __bfloat162float(h);
    lo = v - hi;
}

#define PITCH 144     // 72 bf16 rows (K=64 staging tiles), conflict-free ldmatrix
#define PITCH2 80     // 40 bf16 rows (K=32 B chunks), conflict-free ldmatrix
#define PITCHA 656    // 328 bf16 rows (K=320 A region), 41x16B odd -> conflict-free

// ---------------------------------------------------------------------------
// Pre-split gen1_w / gen2_w into padded bf16 hi/lo
// ---------------------------------------------------------------------------
__global__ void split_w_kernel(const float* __restrict__ gen1_w,
                               const float* __restrict__ gen2_w)
{
    int i = blockIdx.x * blockDim.x + threadIdx.x;
    if (i < NHP * NHP) {
        int n = i / NHP, k = i % NHP;
        float v = (n < NH && k < NH) ? gen2_w[n * NH + k] : 0.f;
        float h, l; split_bf(v, h, l);
        g_g2w_hi[i] = __float2bfloat16(h);
        g_g2w_lo[i] = __float2bfloat16(l);
    }
    if (i < NHP * NL) {
        int n = i / NL, k = i % NL;
        float v = (n < NH) ? gen1_w[n * NL + k] : 0.f;
        float h, l; split_bf(v, h, l);
        g_g1w_hi[i] = __float2bfloat16(h);
        g_g1w_lo[i] = __float2bfloat16(l);
    }
}

// ---------------------------------------------------------------------------
// Fused encoder: 64 CTAs x 4 batch rows. Writes z, z_mean, z_log_var.
// ---------------------------------------------------------------------------
__global__ void __launch_bounds__(256)
encoder_kernel(const float* __restrict__ x,   const float* __restrict__ eps,
               const float* __restrict__ w1,  const float* __restrict__ b1,
               const float* __restrict__ w2,  const float* __restrict__ b2,
               const float* __restrict__ zmw, const float* __restrict__ zmb,
               const float* __restrict__ zvw, const float* __restrict__ zvb,
               float* __restrict__ z, float* __restrict__ z_mean,
               float* __restrict__ z_lv)
{
    __shared__ float xs[4 * 512];
    __shared__ float h1s[4 * 304];
    __shared__ float h2s[4 * 304];
    __shared__ float zms[4 * 64];
    __shared__ float zvs[4 * 64];

    const int tid = threadIdx.x;
    const int r0 = blockIdx.x * 4;

    for (int i = tid; i < 4 * 512; i += 256) {
        int r = i >> 9, k = i & 511;
        xs[i] = x[(r0 + r) * 512 + k];
    }
    __syncthreads();

    for (int n = tid; n < NH; n += 256) {
        float acc[4] = {0, 0, 0, 0};
        const float4* wp = reinterpret_cast<const float4*>(w1 + n * 512);
        for (int kq = 0; kq < 128; kq++) {
            float4 w = wp[kq];
#pragma unroll
            for (int r = 0; r < 4; r++) {
                float4 xv = *reinterpret_cast<const float4*>(&xs[r * 512 + kq * 4]);
                acc[r] += w.x * xv.x + w.y * xv.y + w.z * xv.z + w.w * xv.w;
            }
        }
        float bb = b1[n];
#pragma unroll
        for (int r = 0; r < 4; r++) h1s[r * 304 + n] = fmaxf(acc[r] + bb, 0.f);
    }
    __syncthreads();

    for (int n = tid; n < NH; n += 256) {
        float acc[4] = {0, 0, 0, 0};
        const float4* wp = reinterpret_cast<const float4*>(w2 + n * 300);
        for (int kq = 0; kq < 75; kq++) {
            float4 w = wp[kq];
#pragma unroll
            for (int r = 0; r < 4; r++) {
                float4 hv = *reinterpret_cast<const float4*>(&h1s[r * 304 + kq * 4]);
                acc[r] += w.x * hv.x + w.y * hv.y + w.z * hv.z + w.w * hv.w;
            }
        }
        float bb = b2[n];
#pragma unroll
        for (int r = 0; r < 4; r++) h2s[r * 304 + n] = fmaxf(acc[r] + bb, 0.f);
    }
    __syncthreads();

    if (tid < 128) {
        int n = tid & 63;
        const float* wrow = (tid < 64) ? (zmw + n * 300) : (zvw + n * 300);
        float bb = (tid < 64) ? zmb[n] : zvb[n];
        float acc[4] = {0, 0, 0, 0};
        const float4* wp = reinterpret_cast<const float4*>(wrow);
        for (int kq = 0; kq < 75; kq++) {
            float4 w = wp[kq];
#pragma unroll
            for (int r = 0; r < 4; r++) {
                float4 hv = *reinterpret_cast<const float4*>(&h2s[r * 304 + kq * 4]);
                acc[r] += w.x * hv.x + w.y * hv.y + w.z * hv.z + w.w * hv.w;
            }
        }
#pragma unroll
        for (int r = 0; r < 4; r++) {
            float v = acc[r] + bb;
            int m = r0 + r;
            if (tid < 64) { zms[r * 64 + n] = v; z_mean[m * 64 + n] = v; }
            else          { zvs[r * 64 + n] = v; z_lv[m * 64 + n] = v; }
        }
    }
    __syncthreads();

    if (tid < 64) {
        int n = tid;
#pragma unroll
        for (int r = 0; r < 4; r++) {
            int m = r0 + r;
            z[m * 64 + n] = zms[r * 64 + n] + eps[m * 64 + n] * expf(0.5f * zvs[r * 64 + n]);
        }
    }
}

// ---------------------------------------------------------------------------
// Fused decoder: one CTA = 64 rows (one b, 64 consecutive d).
//   Phase 1: g1 = relu((z[b].*W[d]) @ gen1_w^T)  -> split bf16 in SMEM A-region
//   Phase 2: g2 = relu(g1 @ gen2_w^T + b); x_mean = g2 . head_w[d] + head_b[d]
// grid = 2048, 256 threads, 8 warps = 2 rowgroups(32r = 2 m-tiles) x 4 n-quarters.
// acc[2][10][4] = 80 regs/thread. SMEM ~191 KB (same layout as R13).
// ---------------------------------------------------------------------------
static constexpr uint32_t A_HI  = 0;                         // 64*656 = 41984
static constexpr uint32_t A_LO  = 41984;
static constexpr uint32_t SCR   = 83968;
// phase-1 overlay of SCR:
static constexpr uint32_t P1_ZH  = SCR;                      // 64*144  = 9216
static constexpr uint32_t P1_ZL  = SCR + 9216;
static constexpr uint32_t P1_WH  = SCR + 18432;              // 320*144 = 46080
static constexpr uint32_t P1_WL  = SCR + 64512;              // end SCR+110592
// phase-2 overlay of SCR: B chunks [2 bufs][320*80] hi/lo
static constexpr uint32_t P2_BH  = SCR;                      // + buf*25600
static constexpr uint32_t P2_BL  = SCR + 51200;              // + buf*25600
static constexpr uint32_t GB_OFF = SCR + 110592;             // 304 floats
static constexpr uint32_t FUSED_SMEM = GB_OFF + 1216;        // 195776

__global__ void __launch_bounds__(256, 1)
decoder_kernel(const float* __restrict__ z, const float* __restrict__ W,
               const float* __restrict__ gen2_b,
               const float* __restrict__ head_w,
               const float* __restrict__ head_b,
               float* __restrict__ x_mean)
{
    extern __shared__ char sm[];
    const uint32_t sb = smem_u32(sm);
    float* g2bs = reinterpret_cast<float*>(sm + GB_OFF);
    const int tid  = threadIdx.x;
    const int wid  = tid >> 5;
    const int lane = tid & 31;
    const int g = lane >> 2, c = lane & 3;

    const int m0 = blockIdx.x * 64;
    const int b  = m0 >> 9;
    const int d0 = m0 & 511;

    const int rg = wid >> 2;          // rowgroup: local rows rg*32 .. +31 (2 mt)
    const int nq = wid & 3;           // n quarter: [nq*80, +80) = 10 n-tiles
    const int mrow0 = rg * 32;
    const int nbase = nq * 80;

    // per-lane ldmatrix offsets for the three pitches
    const uint32_t xoff1 = (uint32_t)((lane & 15) * PITCH  + ((lane >> 4) << 4));
    const uint32_t xoffA = (uint32_t)((lane & 15) * PITCHA + ((lane >> 4) << 4));
    const uint32_t xoffB = (uint32_t)((lane & 15) * PITCH2 + ((lane >> 4) << 4));

    // ---- prologue staging: bias, masked z (split), gen1_w (split) ----
    for (int i = tid; i < 304; i += 256)
        g2bs[i] = (i < 300) ? gen2_b[i] : 0.f;

    for (int idx = tid; idx < 64 * 16; idx += 256) {
        int r = idx >> 4, lq = idx & 15;
        float4 wv = *reinterpret_cast<const float4*>(&W[(d0 + r) * 64 + lq * 4]);
        float4 zv = *reinterpret_cast<const float4*>(&z[b * 64 + lq * 4]);
        float v0 = wv.x * zv.x, v1 = wv.y * zv.y, v2 = wv.z * zv.z, v3 = wv.w * zv.w;
        float h0, l0, h1, l1, h2, l2, h3, l3;
        split_bf(v0, h0, l0); split_bf(v1, h1, l1);
        split_bf(v2, h2, l2); split_bf(v3, h3, l3);
        uint2 hi2 = make_uint2(pack2bf(h0, h1), pack2bf(h2, h3));
        uint2 lo2 = make_uint2(pack2bf(l0, l1), pack2bf(l2, l3));
        uint32_t off = (uint32_t)(r * PITCH + lq * 8);
        *reinterpret_cast<uint2*>(sm + P1_ZH + off) = hi2;
        *reinterpret_cast<uint2*>(sm + P1_ZL + off) = lo2;
    }
    {
        const uint4* wh = reinterpret_cast<const uint4*>(g_g1w_hi);
        const uint4* wl = reinterpret_cast<const uint4*>(g_g1w_lo);
        for (int idx = tid; idx < 320 * 8; idx += 256) {
            int n = idx >> 3, kq = idx & 7;
            uint32_t off = (uint32_t)(n * PITCH + kq * 16);
            *reinterpret_cast<uint4*>(sm + P1_WH + off) = wh[idx];
            *reinterpret_cast<uint4*>(sm + P1_WL + off) = wl[idx];
        }
    }
    __syncthreads();

    float acc[2][10][4];
#pragma unroll
    for (int mi = 0; mi < 2; mi++)
#pragma unroll
        for (int j = 0; j < 10; j++)
#pragma unroll
            for (int e = 0; e < 4; e++) acc[mi][j][e] = 0.f;

    // ---- phase 1 mainloop: K = 64 ----
#pragma unroll
    for (int kt = 0; kt < 4; kt++) {
        uint32_t Ah[2][4], Al[2][4];
#pragma unroll
        for (int mi = 0; mi < 2; mi++) {
            uint32_t base = (uint32_t)((mrow0 + mi * 16) * PITCH + kt * 32) + xoff1;
            ldsm_x4(Ah[mi], sb + P1_ZH + base);
            ldsm_x4(Al[mi], sb + P1_ZL + base);
        }
#pragma unroll
        for (int jp = 0; jp < 5; jp++) {
            uint32_t bbad = (uint32_t)((nbase + jp * 16) * PITCH + kt * 32) + xoff1;
            uint32_t bhi[4], blo[4];
            ldsm_x4(bhi, sb + P1_WH + bbad);
            ldsm_x4(blo, sb + P1_WL + bbad);
            const int j0 = 2 * jp, j1 = 2 * jp + 1;
#pragma unroll
            for (int mi = 0; mi < 2; mi++) {
                mma16816(acc[mi][j0], Ah[mi], bhi[0], bhi[2]);
                mma16816(acc[mi][j1], Ah[mi], bhi[1], bhi[3]);
            }
#pragma unroll
            for (int mi = 0; mi < 2; mi++) {
                mma16816(acc[mi][j0], Al[mi], bhi[0], bhi[2]);
                mma16816(acc[mi][j1], Al[mi], bhi[1], bhi[3]);
            }
#pragma unroll
            for (int mi = 0; mi < 2; mi++) {
                mma16816(acc[mi][j0], Ah[mi], blo[0], blo[2]);
                mma16816(acc[mi][j1], Ah[mi], blo[1], blo[3]);
            }
        }
    }

    // ---- phase 1 epilogue: relu + split -> SMEM A region ----
#pragma unroll
    for (int mi = 0; mi < 2; mi++) {
        const int r0 = mrow0 + mi * 16 + g;   // local rows
        const int r1 = r0 + 8;
#pragma unroll
        for (int j = 0; j < 10; j++) {
            const int n0 = nbase + j * 8 + 2 * c;
            float h0f, l0f, h1f, l1f, h2f, l2f, h3f, l3f;
            split_bf(fmaxf(acc[mi][j][0], 0.f), h0f, l0f);
            split_bf(fmaxf(acc[mi][j][1], 0.f), h1f, l1f);
            split_bf(fmaxf(acc[mi][j][2], 0.f), h2f, l2f);
            split_bf(fmaxf(acc[mi][j][3], 0.f), h3f, l3f);
            uint32_t o0 = (uint32_t)(r0 * PITCHA + n0 * 2);
            uint32_t o1 = (uint32_t)(r1 * PITCHA + n0 * 2);
            *reinterpret_cast<uint32_t*>(sm + A_HI + o0) = pack2bf(h0f, h1f);
            *reinterpret_cast<uint32_t*>(sm + A_LO + o0) = pack2bf(l0f, l1f);
            *reinterpret_cast<uint32_t*>(sm + A_HI + o1) = pack2bf(h2f, h3f);
            *reinterpret_cast<uint32_t*>(sm + A_LO + o1) = pack2bf(l2f, l3f);
        }
    }
    __syncthreads();   // gen1_w reads + A writes done; scratch now free for B

    // ---- phase 2: K = 320 in 10 cp.async double-buffered K32 chunks ----
    const uint4* bhg = reinterpret_cast<const uint4*>(g_g2w_hi);
    const uint4* blg = reinterpret_cast<const uint4*>(g_g2w_lo);

    auto stage = [&](int kc, int buf) {
        uint32_t bh = sb + P2_BH + buf * 25600;
        uint32_t bl = sb + P2_BL + buf * 25600;
        for (int e = tid; e < 2560; e += 256) {
            int idx = e % 1280;
            int r = idx >> 2, kq = idx & 3;
            uint32_t off = (uint32_t)(r * PITCH2 + kq * 16);
            size_t gi = (size_t)r * 40 + kc * 4 + kq;
            if (e < 1280) cpasync16(bh + off, bhg + gi);
            else          cpasync16(bl + off, blg + gi);
        }
    };

#pragma unroll
    for (int mi = 0; mi < 2; mi++)
#pragma unroll
        for (int j = 0; j < 10; j++)
#pragma unroll
            for (int e = 0; e < 4; e++) acc[mi][j][e] = 0.f;

    stage(0, 0); CP_COMMIT();

#pragma unroll 1
    for (int kc = 0; kc < 10; kc++) {
        const int buf = kc & 1;
        if (kc + 1 < 10) { stage(kc + 1, buf ^ 1); CP_COMMIT(); CP_WAIT(1); }
        else             { CP_WAIT(0); }
        __syncthreads();

        uint32_t bh = sb + P2_BH + buf * 25600;
        uint32_t bl = sb + P2_BL + buf * 25600;

#pragma unroll
        for (int kt = 0; kt < 2; kt++) {
            uint32_t Ah[2][4], Al[2][4];
#pragma unroll
            for (int mi = 0; mi < 2; mi++) {
                uint32_t abase = (uint32_t)((mrow0 + mi * 16) * PITCHA
                                            + kc * 64 + kt * 32) + xoffA;
                ldsm_x4(Ah[mi], sb + A_HI + abase);
                ldsm_x4(Al[mi], sb + A_LO + abase);
            }
#pragma unroll
            for (int jp = 0; jp < 5; jp++) {
                uint32_t bbad = (uint32_t)((nbase + jp * 16) * PITCH2 + kt * 32) + xoffB;
                uint32_t bhi[4], blo[4];
                ldsm_x4(bhi, bh + bbad);
                ldsm_x4(blo, bl + bbad);
                const int j0 = 2 * jp, j1 = 2 * jp + 1;
#pragma unroll
                for (int mi = 0; mi < 2; mi++) {
                    mma16816(acc[mi][j0], Ah[mi], bhi[0], bhi[2]);
                    mma16816(acc[mi][j1], Ah[mi], bhi[1], bhi[3]);
                }
#pragma unroll
                for (int mi = 0; mi < 2; mi++) {
                    mma16816(acc[mi][j0], Al[mi], bhi[0], bhi[2]);
                    mma16816(acc[mi][j1], Al[mi], bhi[1], bhi[3]);
                }
#pragma unroll
                for (int mi = 0; mi < 2; mi++) {
                    mma16816(acc[mi][j0], Ah[mi], blo[0], blo[2]);
                    mma16816(acc[mi][j1], Ah[mi], blo[1], blo[3]);
                }
            }
        }
        __syncthreads();   // buffer consumed before it is re-staged
    }

    // ---- epilogue: relu + bias, dot with head_w, quad-reduce, accumulate ----
#pragma unroll
    for (int mi = 0; mi < 2; mi++) {
        const int r0 = m0 + mrow0 + mi * 16 + g;
        const int r1 = r0 + 8;
        const float* hw0 = head_w + (size_t)(r0 & 511) * 300;
        const float* hw1 = head_w + (size_t)(r1 & 511) * 300;
        float x0 = 0.f, x1 = 0.f;
#pragma unroll
        for (int j = 0; j < 10; j++) {
            const int n0 = nbase + j * 8 + 2 * c;
            if (n0 < 300) {
                float bb = g2bs[n0];
                float v0 = fmaxf(acc[mi][j][0] + bb, 0.f);
                float v2 = fmaxf(acc[mi][j][2] + bb, 0.f);
                x0 = fmaf(v0, hw0[n0], x0);
                x1 = fmaf(v2, hw1[n0], x1);
            }
            if (n0 + 1 < 300) {
                float bb = g2bs[n0 + 1];
                float v1 = fmaxf(acc[mi][j][1] + bb, 0.f);
                float v3 = fmaxf(acc[mi][j][3] + bb, 0.f);
                x0 = fmaf(v1, hw0[n0 + 1], x0);
                x1 = fmaf(v3, hw1[n0 + 1], x1);
            }
        }
        x0 += __shfl_xor_sync(0xffffffffu, x0, 1);
        x0 += __shfl_xor_sync(0xffffffffu, x0, 2);
        x1 += __shfl_xor_sync(0xffffffffu, x1, 1);
        x1 += __shfl_xor_sync(0xffffffffu, x1, 2);
        if (c == 0) {
            atomicAdd(&x_mean[r0], x0);
            atomicAdd(&x_mean[r1], x1);
        }
    }
}

// ---------------------------------------------------------------------------
// x_mean init (n-quarters accumulate via atomicAdd; start from head_b)
// ---------------------------------------------------------------------------
__global__ void xinit_kernel(const float* __restrict__ head_b,
                             float* __restrict__ x_mean)
{
    int i = blockIdx.x * blockDim.x + threadIdx.x;
    if (i < MTOT) x_mean[i] = head_b[i & 511];
}

// ---------------------------------------------------------------------------
extern "C" void kernel_launch(void* const* d_in, const int* in_sizes, int n_in,
                              void* d_out, int out_size)
{
    const float* x      = (const float*)d_in[0];
    const float* eps    = (const float*)d_in[1];
    const float* W      = (const float*)d_in[2];
    const float* enc1_w = (const float*)d_in[3];
    const float* enc1_b = (const float*)d_in[4];
    const float* enc2_w = (const float*)d_in[5];
    const float* enc2_b = (const float*)d_in[6];
    const float* zm_w   = (const float*)d_in[7];
    const float* zm_b   = (const float*)d_in[8];
    const float* zv_w   = (const float*)d_in[9];
    const float* zv_b   = (const float*)d_in[10];
    const float* gen1_w = (const float*)d_in[11];
    const float* gen2_w = (const float*)d_in[12];
    const float* gen2_b = (const float*)d_in[13];
    const float* head_w = (const float*)d_in[14];
    const float* head_b = (const float*)d_in[15];

    float* out    = (float*)d_out;
    float* x_mean = out;                 // [256,512]
    float* zbuf   = out + NB * ND;       // [256,64]
    float* z_mean = zbuf + NB * NL;      // [256,64]
    float* z_lv   = z_mean + NB * NL;    // [256,64]

    cudaFuncSetAttribute(decoder_kernel,
                         cudaFuncAttributeMaxDynamicSharedMemorySize,
                         (int)FUSED_SMEM);

    split_w_kernel<<<(NHP * NHP + 255) / 256, 256>>>(gen1_w, gen2_w);
    encoder_kernel<<<64, 256>>>(x, eps, enc1_w, enc1_b, enc2_w, enc2_b,
                                zm_w, zm_b, zv_w, zv_b, zbuf, z_mean, z_lv);
    xinit_kernel<<<(MTOT + 255) / 256, 256>>>(head_b, x_mean);
    decoder_kernel<<<MTOT / 64, 256, FUSED_SMEM>>>(zbuf, W, gen2_b,
                                                   head_w, head_b, x_mean);
}

// round 15
// speedup vs baseline: 1.0494x; 1.0494x over previous
#include <cuda_runtime.h>
#include <cuda_bf16.h>
#include <math.h>
#include <stdint.h>

// ---------------------------------------------------------------------------
// Problem dims
// ---------------------------------------------------------------------------
#define NB 256
#define ND 512
#define NL 64
#define NH 300
#define NHP 320                   // H padded to 5 * 64
#define MTOT (NB * ND)            // 131072 decoder rows (m = b*512 + d)

// ---------------------------------------------------------------------------
// Scratch (__device__ globals — no cudaMalloc allowed), 16B-aligned
// ---------------------------------------------------------------------------
__device__ __align__(16) __nv_bfloat16 g_g1w_hi[NHP * NL];
__device__ __align__(16) __nv_bfloat16 g_g1w_lo[NHP * NL];
__device__ __align__(16) __nv_bfloat16 g_g2w_hi[NHP * NHP];
__device__ __align__(16) __nv_bfloat16 g_g2w_lo[NHP * NHP];

// ---------------------------------------------------------------------------
// mma.sync / ldmatrix / cp.async helpers (baseline PTX, legal on sm_103)
// ---------------------------------------------------------------------------
__device__ __forceinline__ uint32_t smem_u32(const void* p) {
    uint32_t a;
    asm("{ .reg .u64 t; cvta.to.shared.u64 t, %1; cvt.u32.u64 %0, t; }"
        : "=r"(a) : "l"(p));
    return a;
}

__device__ __forceinline__ void mma16816(float* c, const uint32_t* a,
                                         uint32_t b0, uint32_t b1) {
    asm volatile(
        "mma.sync.aligned.m16n8k16.row.col.f32.bf16.bf16.f32 "
        "{%0,%1,%2,%3}, {%4,%5,%6,%7}, {%8,%9}, {%0,%1,%2,%3};"
        : "+f"(c[0]), "+f"(c[1]), "+f"(c[2]), "+f"(c[3])
        : "r"(a[0]), "r"(a[1]), "r"(a[2]), "r"(a[3]), "r"(b0), "r"(b1));
}

__device__ __forceinline__ void ldsm_x4(uint32_t* r, uint32_t addr) {
    asm volatile("ldmatrix.sync.aligned.m8n8.x4.shared.b16 {%0,%1,%2,%3}, [%4];"
                 : "=r"(r[0]), "=r"(r[1]), "=r"(r[2]), "=r"(r[3]) : "r"(addr));
}

__device__ __forceinline__ void cpasync16(uint32_t saddr, const void* gptr) {
    asm volatile("cp.async.cg.shared.global [%0], [%1], 16;"
                 :: "r"(saddr), "l"(gptr) : "memory");
}
#define CP_COMMIT() asm volatile("cp.async.commit_group;" ::: "memory")
#define CP_WAIT(n)  asm volatile("cp.async.wait_group %0;" :: "n"(n) : "memory")

__device__ __forceinline__ uint32_t pack2bf(float a, float b) {
    __nv_bfloat162 t = __floats2bfloat162_rn(a, b);
    return *reinterpret_cast<uint32_t*>(&t);
}

__device__ __forceinline__ void split_bf(float v, float& hi, float& lo) {
    __nv_bfloat16 h = __float2bfloat16(v);
    hi = __bfloat162float(h);
    lo = v - hi;
}

#define PITCH 144     // 72 bf16 rows (K=64 staging tiles), conflict-free ldmatrix
#define PITCH2 80     // 40 bf16 rows (K=32 B chunks), conflict-free ldmatrix
#define PITCHA 656    // 328 bf16 rows (K=320 A region), 41x16B odd -> conflict-free

// ---------------------------------------------------------------------------
// Pre-split gen1_w / gen2_w into padded bf16 hi/lo
// ---------------------------------------------------------------------------
__global__ void split_w_kernel(const float* __restrict__ gen1_w,
                               const float* __restrict__ gen2_w)
{
    int i = blockIdx.x * blockDim.x + threadIdx.x;
    if (i < NHP * NHP) {
        int n = i / NHP, k = i % NHP;
        float v = (n < NH && k < NH) ? gen2_w[n * NH + k] : 0.f;
        float h, l; split_bf(v, h, l);
        g_g2w_hi[i] = __float2bfloat16(h);
        g_g2w_lo[i] = __float2bfloat16(l);
    }
    if (i < NHP * NL) {
        int n = i / NL, k = i % NL;
        float v = (n < NH) ? gen1_w[n * NL + k] : 0.f;
        float h, l; split_bf(v, h, l);
        g_g1w_hi[i] = __float2bfloat16(h);
        g_g1w_lo[i] = __float2bfloat16(l);
    }
}

// ---------------------------------------------------------------------------
// Fused encoder: 64 CTAs x 4 batch rows. Writes z, z_mean, z_log_var.
// ---------------------------------------------------------------------------
__global__ void __launch_bounds__(256)
encoder_kernel(const float* __restrict__ x,   const float* __restrict__ eps,
               const float* __restrict__ w1,  const float* __restrict__ b1,
               const float* __restrict__ w2,  const float* __restrict__ b2,
               const float* __restrict__ zmw, const float* __restrict__ zmb,
               const float* __restrict__ zvw, const float* __restrict__ zvb,
               float* __restrict__ z, float* __restrict__ z_mean,
               float* __restrict__ z_lv)
{
    __shared__ float xs[4 * 512];
    __shared__ float h1s[4 * 304];
    __shared__ float h2s[4 * 304];
    __shared__ float zms[4 * 64];
    __shared__ float zvs[4 * 64];

    const int tid = threadIdx.x;
    const int r0 = blockIdx.x * 4;

    for (int i = tid; i < 4 * 512; i += 256) {
        int r = i >> 9, k = i & 511;
        xs[i] = x[(r0 + r) * 512 + k];
    }
    __syncthreads();

    for (int n = tid; n < NH; n += 256) {
        float acc[4] = {0, 0, 0, 0};
        const float4* wp = reinterpret_cast<const float4*>(w1 + n * 512);
        for (int kq = 0; kq < 128; kq++) {
            float4 w = wp[kq];
#pragma unroll
            for (int r = 0; r < 4; r++) {
                float4 xv = *reinterpret_cast<const float4*>(&xs[r * 512 + kq * 4]);
                acc[r] += w.x * xv.x + w.y * xv.y + w.z * xv.z + w.w * xv.w;
            }
        }
        float bb = b1[n];
#pragma unroll
        for (int r = 0; r < 4; r++) h1s[r * 304 + n] = fmaxf(acc[r] + bb, 0.f);
    }
    __syncthreads();

    for (int n = tid; n < NH; n += 256) {
        float acc[4] = {0, 0, 0, 0};
        const float4* wp = reinterpret_cast<const float4*>(w2 + n * 300);
        for (int kq = 0; kq < 75; kq++) {
            float4 w = wp[kq];
#pragma unroll
            for (int r = 0; r < 4; r++) {
                float4 hv = *reinterpret_cast<const float4*>(&h1s[r * 304 + kq * 4]);
                acc[r] += w.x * hv.x + w.y * hv.y + w.z * hv.z + w.w * hv.w;
            }
        }
        float bb = b2[n];
#pragma unroll
        for (int r = 0; r < 4; r++) h2s[r * 304 + n] = fmaxf(acc[r] + bb, 0.f);
    }
    __syncthreads();

    if (tid < 128) {
        int n = tid & 63;
        const float* wrow = (tid < 64) ? (zmw + n * 300) : (zvw + n * 300);
        float bb = (tid < 64) ? zmb[n] : zvb[n];
        float acc[4] = {0, 0, 0, 0};
        const float4* wp = reinterpret_cast<const float4*>(wrow);
        for (int kq = 0; kq < 75; kq++) {
            float4 w = wp[kq];
#pragma unroll
            for (int r = 0; r < 4; r++) {
                float4 hv = *reinterpret_cast<const float4*>(&h2s[r * 304 + kq * 4]);
                acc[r] += w.x * hv.x + w.y * hv.y + w.z * hv.z + w.w * hv.w;
            }
        }
#pragma unroll
        for (int r = 0; r < 4; r++) {
            float v = acc[r] + bb;
            int m = r0 + r;
            if (tid < 64) { zms[r * 64 + n] = v; z_mean[m * 64 + n] = v; }
            else          { zvs[r * 64 + n] = v; z_lv[m * 64 + n] = v; }
        }
    }
    __syncthreads();

    if (tid < 64) {
        int n = tid;
#pragma unroll
        for (int r = 0; r < 4; r++) {
            int m = r0 + r;
            z[m * 64 + n] = zms[r * 64 + n] + eps[m * 64 + n] * expf(0.5f * zvs[r * 64 + n]);
        }
    }
}

// ---------------------------------------------------------------------------
// Fused decoder: one CTA = 64 rows (one b, 64 consecutive d).
//   Phase 1: g1 = relu((z[b].*W[d]) @ gen1_w^T)  -> split bf16 in SMEM A-region
//   Phase 2: g2 = relu(g1 @ gen2_w^T + b); x_mean = g2 . head_w[d] + head_b[d]
// grid = 2048, 512 threads, 16 warps = 4 rowgroups(16r) x 4 n-quarters(80n).
// Dead-padding MMAs (n>=304, K>=304) are skipped; all are zero by construction.
// SMEM ~191 KB: A hi/lo [64][328] + overlaid scratch + bias.
// ---------------------------------------------------------------------------
static constexpr uint32_t A_HI  = 0;                         // 64*656 = 41984
static constexpr uint32_t A_LO  = 41984;
static constexpr uint32_t SCR   = 83968;
// phase-1 overlay of SCR:
static constexpr uint32_t P1_ZH  = SCR;                      // 64*144  = 9216
static constexpr uint32_t P1_ZL  = SCR + 9216;
static constexpr uint32_t P1_WH  = SCR + 18432;              // 320*144 = 46080
static constexpr uint32_t P1_WL  = SCR + 64512;              // end SCR+110592
// phase-2 overlay of SCR: B chunks [2 bufs][320*80] hi/lo
static constexpr uint32_t P2_BH  = SCR;                      // + buf*25600
static constexpr uint32_t P2_BL  = SCR + 51200;              // + buf*25600
static constexpr uint32_t GB_OFF = SCR + 110592;             // 304 floats
static constexpr uint32_t FUSED_SMEM = GB_OFF + 1216;        // 195776

__global__ void __launch_bounds__(512, 1)
decoder_kernel(const float* __restrict__ z, const float* __restrict__ W,
               const float* __restrict__ gen2_b,
               const float* __restrict__ head_w,
               const float* __restrict__ head_b,
               float* __restrict__ x_mean)
{
    extern __shared__ char sm[];
    const uint32_t sb = smem_u32(sm);
    float* g2bs = reinterpret_cast<float*>(sm + GB_OFF);
    const int tid  = threadIdx.x;
    const int wid  = tid >> 5;
    const int lane = tid & 31;
    const int g = lane >> 2, c = lane & 3;

    const int m0 = blockIdx.x * 64;
    const int b  = m0 >> 9;
    const int d0 = m0 & 511;

    const int rg = wid >> 2;          // rowgroup: local rows rg*16 .. +15
    const int nq = wid & 3;           // n quarter: [nq*80, +80) = 10 n-tiles
    const int mrow0 = rg * 16;
    const int nbase = nq * 80;
    // nq==3 covers n 240..319; its jp==4 pair (n 304..319) is entirely dead
    const int jpmax = (nq == 3) ? 4 : 5;

    // per-lane ldmatrix offsets for the three pitches
    const uint32_t xoff1 = (uint32_t)((lane & 15) * PITCH  + ((lane >> 4) << 4));
    const uint32_t xoffA = (uint32_t)((lane & 15) * PITCHA + ((lane >> 4) << 4));
    const uint32_t xoffB = (uint32_t)((lane & 15) * PITCH2 + ((lane >> 4) << 4));

    // ---- prologue staging: bias, masked z (split), gen1_w (split) ----
    for (int i = tid; i < 304; i += 512)
        g2bs[i] = (i < 300) ? gen2_b[i] : 0.f;

    for (int idx = tid; idx < 64 * 16; idx += 512) {
        int r = idx >> 4, lq = idx & 15;
        float4 wv = *reinterpret_cast<const float4*>(&W[(d0 + r) * 64 + lq * 4]);
        float4 zv = *reinterpret_cast<const float4*>(&z[b * 64 + lq * 4]);
        float v0 = wv.x * zv.x, v1 = wv.y * zv.y, v2 = wv.z * zv.z, v3 = wv.w * zv.w;
        float h0, l0, h1, l1, h2, l2, h3, l3;
        split_bf(v0, h0, l0); split_bf(v1, h1, l1);
        split_bf(v2, h2, l2); split_bf(v3, h3, l3);
        uint2 hi2 = make_uint2(pack2bf(h0, h1), pack2bf(h2, h3));
        uint2 lo2 = make_uint2(pack2bf(l0, l1), pack2bf(l2, l3));
        uint32_t off = (uint32_t)(r * PITCH + lq * 8);
        *reinterpret_cast<uint2*>(sm + P1_ZH + off) = hi2;
        *reinterpret_cast<uint2*>(sm + P1_ZL + off) = lo2;
    }
    {
        const uint4* wh = reinterpret_cast<const uint4*>(g_g1w_hi);
        const uint4* wl = reinterpret_cast<const uint4*>(g_g1w_lo);
        for (int idx = tid; idx < 320 * 8; idx += 512) {
            int n = idx >> 3, kq = idx & 7;
            uint32_t off = (uint32_t)(n * PITCH + kq * 16);
            *reinterpret_cast<uint4*>(sm + P1_WH + off) = wh[idx];
            *reinterpret_cast<uint4*>(sm + P1_WL + off) = wl[idx];
        }
    }
    __syncthreads();

    float acc[10][4];
#pragma unroll
    for (int j = 0; j < 10; j++)
#pragma unroll
        for (int e = 0; e < 4; e++) acc[j][e] = 0.f;

    // ---- phase 1 mainloop: K = 64 (skip dead n>=304 pair for nq==3) ----
#pragma unroll
    for (int kt = 0; kt < 4; kt++) {
        uint32_t Ah[4], Al[4];
        uint32_t base = (uint32_t)(mrow0 * PITCH + kt * 32) + xoff1;
        ldsm_x4(Ah, sb + P1_ZH + base);
        ldsm_x4(Al, sb + P1_ZL + base);
#pragma unroll
        for (int jp = 0; jp < 5; jp++) {
            if (jp >= jpmax) break;
            uint32_t bbad = (uint32_t)((nbase + jp * 16) * PITCH + kt * 32) + xoff1;
            uint32_t bhi[4], blo[4];
            ldsm_x4(bhi, sb + P1_WH + bbad);
            ldsm_x4(blo, sb + P1_WL + bbad);
            const int j0 = 2 * jp, j1 = 2 * jp + 1;
            mma16816(acc[j0], Ah, bhi[0], bhi[2]);
            mma16816(acc[j1], Ah, bhi[1], bhi[3]);
            mma16816(acc[j0], Al, bhi[0], bhi[2]);
            mma16816(acc[j1], Al, bhi[1], bhi[3]);
            mma16816(acc[j0], Ah, blo[0], blo[2]);
            mma16816(acc[j1], Ah, blo[1], blo[3]);
        }
    }

    // ---- phase 1 epilogue: relu + split -> SMEM A region ----
    // (nq==3 j=8,9 write zeros from the zero-init accs; those A cols are only
    //  touched by the skipped kc==9/kt==1 phase-2 step, so writes are optional;
    //  we keep them for layout hygiene.)
    {
        const int r0 = mrow0 + g;        // local rows
        const int r1 = r0 + 8;
#pragma unroll
        for (int j = 0; j < 10; j++) {
            const int n0 = nbase + j * 8 + 2 * c;
            float h0f, l0f, h1f, l1f, h2f, l2f, h3f, l3f;
            split_bf(fmaxf(acc[j][0], 0.f), h0f, l0f);
            split_bf(fmaxf(acc[j][1], 0.f), h1f, l1f);
            split_bf(fmaxf(acc[j][2], 0.f), h2f, l2f);
            split_bf(fmaxf(acc[j][3], 0.f), h3f, l3f);
            uint32_t o0 = (uint32_t)(r0 * PITCHA + n0 * 2);
            uint32_t o1 = (uint32_t)(r1 * PITCHA + n0 * 2);
            *reinterpret_cast<uint32_t*>(sm + A_HI + o0) = pack2bf(h0f, h1f);
            *reinterpret_cast<uint32_t*>(sm + A_LO + o0) = pack2bf(l0f, l1f);
            *reinterpret_cast<uint32_t*>(sm + A_HI + o1) = pack2bf(h2f, h3f);
            *reinterpret_cast<uint32_t*>(sm + A_LO + o1) = pack2bf(l2f, l3f);
        }
    }
    __syncthreads();   // gen1_w reads + A writes done; scratch now free for B

    // ---- phase 2: K = 320 in 10 cp.async K32 chunks, 1 barrier per chunk ----
    const uint4* bhg = reinterpret_cast<const uint4*>(g_g2w_hi);
    const uint4* blg = reinterpret_cast<const uint4*>(g_g2w_lo);

    auto stage = [&](int kc, int buf) {
        uint32_t bh = sb + P2_BH + buf * 25600;
        uint32_t bl = sb + P2_BL + buf * 25600;
        for (int e = tid; e < 2560; e += 512) {
            int idx = e % 1280;
            int r = idx >> 2, kq = idx & 3;
            uint32_t off = (uint32_t)(r * PITCH2 + kq * 16);
            size_t gi = (size_t)r * 40 + kc * 4 + kq;
            if (e < 1280) cpasync16(bh + off, bhg + gi);
            else          cpasync16(bl + off, blg + gi);
        }
    };

#pragma unroll
    for (int j = 0; j < 10; j++)
#pragma unroll
        for (int e = 0; e < 4; e++) acc[j][e] = 0.f;

    stage(0, 0); CP_COMMIT();
    stage(1, 1); CP_COMMIT();
    CP_WAIT(1); __syncthreads();     // chunk 0 ready

#pragma unroll 1
    for (int kc = 0; kc < 10; kc++) {
        const int buf = kc & 1;
        uint32_t bh = sb + P2_BH + buf * 25600;
        uint32_t bl = sb + P2_BL + buf * 25600;

#pragma unroll
        for (int kt = 0; kt < 2; kt++) {
            if (kc == 9 && kt == 1) break;   // K 304..319 is all zeros — skip
            uint32_t Ah[4], Al[4];
            uint32_t abase = (uint32_t)(mrow0 * PITCHA + kc * 64 + kt * 32) + xoffA;
            ldsm_x4(Ah, sb + A_HI + abase);
            ldsm_x4(Al, sb + A_LO + abase);
#pragma unroll
            for (int jp = 0; jp < 5; jp++) {
                if (jp >= jpmax) break;      // n 304..319 dead for nq==3
                uint32_t bbad = (uint32_t)((nbase + jp * 16) * PITCH2 + kt * 32) + xoffB;
                uint32_t bhi[4], blo[4];
                ldsm_x4(bhi, bh + bbad);
                ldsm_x4(blo, bl + bbad);
                const int j0 = 2 * jp, j1 = 2 * jp + 1;
                mma16816(acc[j0], Ah, bhi[0], bhi[2]);
                mma16816(acc[j1], Ah, bhi[1], bhi[3]);
                mma16816(acc[j0], Al, bhi[0], bhi[2]);
                mma16816(acc[j1], Al, bhi[1], bhi[3]);
                mma16816(acc[j0], Ah, blo[0], blo[2]);
                mma16816(acc[j1], Ah, blo[1], blo[3]);
            }
        }

        if (kc < 9) {
            CP_WAIT(0);          // chunk kc+1 landed while we computed kc
            __syncthreads();     // publish kc+1; buf kc now free for restage
            if (kc < 8) { stage(kc + 2, buf); CP_COMMIT(); }
        }
    }

    // ---- epilogue: relu + bias, dot with head_w, quad-reduce, accumulate ----
    {
        const int r0 = m0 + mrow0 + g;
        const int r1 = r0 + 8;
        const float* hw0 = head_w + (size_t)(r0 & 511) * 300;
        const float* hw1 = head_w + (size_t)(r1 & 511) * 300;
        float x0 = 0.f, x1 = 0.f;
#pragma unroll
        for (int j = 0; j < 10; j++) {
            const int n0 = nbase + j * 8 + 2 * c;
            if (n0 < 300) {
                float bb = g2bs[n0];
                float v0 = fmaxf(acc[j][0] + bb, 0.f);
                float v2 = fmaxf(acc[j][2] + bb, 0.f);
                x0 = fmaf(v0, hw0[n0], x0);
                x1 = fmaf(v2, hw1[n0], x1);
            }
            if (n0 + 1 < 300) {
                float bb = g2bs[n0 + 1];
                float v1 = fmaxf(acc[j][1] + bb, 0.f);
                float v3 = fmaxf(acc[j][3] + bb, 0.f);
                x0 = fmaf(v1, hw0[n0 + 1], x0);
                x1 = fmaf(v3, hw1[n0 + 1], x1);
            }
        }
        x0 += __shfl_xor_sync(0xffffffffu, x0, 1);
        x0 += __shfl_xor_sync(0xffffffffu, x0, 2);
        x1 += __shfl_xor_sync(0xffffffffu, x1, 1);
        x1 += __shfl_xor_sync(0xffffffffu, x1, 2);
        if (c == 0) {
            atomicAdd(&x_mean[r0], x0);
            atomicAdd(&x_mean[r1], x1);
        }
    }
}

// ---------------------------------------------------------------------------
// x_mean init (n-quarters accumulate via atomicAdd; start from head_b)
// ---------------------------------------------------------------------------
__global__ void xinit_kernel(const float* __restrict__ head_b,
                             float* __restrict__ x_mean)
{
    int i = blockIdx.x * blockDim.x + threadIdx.x;
    if (i < MTOT) x_mean[i] = head_b[i & 511];
}

// ---------------------------------------------------------------------------
extern "C" void kernel_launch(void* const* d_in, const int* in_sizes, int n_in,
                              void* d_out, int out_size)
{
    const float* x      = (const float*)d_in[0];
    const float* eps    = (const float*)d_in[1];
    const float* W      = (const float*)d_in[2];
    const float* enc1_w = (const float*)d_in[3];
    const float* enc1_b = (const float*)d_in[4];
    const float* enc2_w = (const float*)d_in[5];
    const float* enc2_b = (const float*)d_in[6];
    const float* zm_w   = (const float*)d_in[7];
    const float* zm_b   = (const float*)d_in[8];
    const float* zv_w   = (const float*)d_in[9];
    const float* zv_b   = (const float*)d_in[10];
    const float* gen1_w = (const float*)d_in[11];
    const float* gen2_w = (const float*)d_in[12];
    const float* gen2_b = (const float*)d_in[13];
    const float* head_w = (const float*)d_in[14];
    const float* head_b = (const float*)d_in[15];

    float* out    = (float*)d_out;
    float* x_mean = out;                 // [256,512]
    float* zbuf   = out + NB * ND;       // [256,64]
    float* z_mean = zbuf + NB * NL;      // [256,64]
    float* z_lv   = z_mean + NB * NL;    // [256,64]

    cudaFuncSetAttribute(decoder_kernel,
                         cudaFuncAttributeMaxDynamicSharedMemorySize,
                         (int)FUSED_SMEM);

    split_w_kernel<<<(NHP * NHP + 255) / 256, 256>>>(gen1_w, gen2_w);
    encoder_kernel<<<64, 256>>>(x, eps, enc1_w, enc1_b, enc2_w, enc2_b,
                                zm_w, zm_b, zv_w, zv_b, zbuf, z_mean, z_lv);
    xinit_kernel<<<(MTOT + 255) / 256, 256>>>(head_b, x_mean);
    decoder_kernel<<<MTOT / 64, 512, FUSED_SMEM>>>(zbuf, W, gen2_b,
                                                   head_w, head_b, x_mean);
}

// round 16
// speedup vs baseline: 1.0793x; 1.0285x over previous
#include <cuda_runtime.h>
#include <cuda_bf16.h>
#include <math.h>
#include <stdint.h>

// ---------------------------------------------------------------------------
// Problem dims
// ---------------------------------------------------------------------------
#define NB 256
#define ND 512
#define NL 64
#define NH 300
#define NHP 320                   // H padded to 5 * 64
#define MTOT (NB * ND)            // 131072 decoder rows (m = b*512 + d)

// ---------------------------------------------------------------------------
// Scratch (__device__ globals — no cudaMalloc allowed), 16B-aligned
// ---------------------------------------------------------------------------
__device__ __align__(16) __nv_bfloat16 g_g1w_hi[NHP * NL];
__device__ __align__(16) __nv_bfloat16 g_g1w_lo[NHP * NL];
__device__ __align__(16) __nv_bfloat16 g_g2w_hi[NHP * NHP];
__device__ __align__(16) __nv_bfloat16 g_g2w_lo[NHP * NHP];

// ---------------------------------------------------------------------------
// mma.sync / ldmatrix / cp.async helpers (baseline PTX, legal on sm_103)
// ---------------------------------------------------------------------------
__device__ __forceinline__ uint32_t smem_u32(const void* p) {
    uint32_t a;
    asm("{ .reg .u64 t; cvta.to.shared.u64 t, %1; cvt.u32.u64 %0, t; }"
        : "=r"(a) : "l"(p));
    return a;
}

__device__ __forceinline__ void mma16816(float* c, const uint32_t* a,
                                         uint32_t b0, uint32_t b1) {
    asm volatile(
        "mma.sync.aligned.m16n8k16.row.col.f32.bf16.bf16.f32 "
        "{%0,%1,%2,%3}, {%4,%5,%6,%7}, {%8,%9}, {%0,%1,%2,%3};"
        : "+f"(c[0]), "+f"(c[1]), "+f"(c[2]), "+f"(c[3])
        : "r"(a[0]), "r"(a[1]), "r"(a[2]), "r"(a[3]), "r"(b0), "r"(b1));
}

__device__ __forceinline__ void ldsm_x4(uint32_t* r, uint32_t addr) {
    asm volatile("ldmatrix.sync.aligned.m8n8.x4.shared.b16 {%0,%1,%2,%3}, [%4];"
                 : "=r"(r[0]), "=r"(r[1]), "=r"(r[2]), "=r"(r[3]) : "r"(addr));
}

__device__ __forceinline__ void ldsm_x2(uint32_t* r, uint32_t addr) {
    asm volatile("ldmatrix.sync.aligned.m8n8.x2.shared.b16 {%0,%1}, [%2];"
                 : "=r"(r[0]), "=r"(r[1]) : "r"(addr));
}

__device__ __forceinline__ void cpasync16(uint32_t saddr, const void* gptr) {
    asm volatile("cp.async.cg.shared.global [%0], [%1], 16;"
                 :: "r"(saddr), "l"(gptr) : "memory");
}
#define CP_COMMIT() asm volatile("cp.async.commit_group;" ::: "memory")
#define CP_WAIT(n)  asm volatile("cp.async.wait_group %0;" :: "n"(n) : "memory")

__device__ __forceinline__ uint32_t pack2bf(float a, float b) {
    __nv_bfloat162 t = __floats2bfloat162_rn(a, b);
    return *reinterpret_cast<uint32_t*>(&t);
}

__device__ __forceinline__ void split_bf(float v, float& hi, float& lo) {
    __nv_bfloat16 h = __float2bfloat16(v);
    hi = __bfloat162float(h);
    lo = v - hi;
}

#define PITCH 144     // 72 bf16 rows (K=64 staging tiles), conflict-free ldmatrix
#define PITCH2 80     // 40 bf16 rows (K=32 B chunks), conflict-free ldmatrix
#define PITCHA 656    // 328 bf16 rows (K=320 A region), 41x16B odd -> conflict-free

// ---------------------------------------------------------------------------
// Prep kernel: blocks 0..127 = fused encoder (2 batch rows each);
//              blocks 128..527 = weight split + x_mean init.
// ---------------------------------------------------------------------------
__global__ void __launch_bounds__(256)
prep_kernel(const float* __restrict__ x,   const float* __restrict__ eps,
            const float* __restrict__ w1,  const float* __restrict__ b1,
            const float* __restrict__ w2,  const float* __restrict__ b2,
            const float* __restrict__ zmw, const float* __restrict__ zmb,
            const float* __restrict__ zvw, const float* __restrict__ zvb,
            const float* __restrict__ gen1_w, const float* __restrict__ gen2_w,
            const float* __restrict__ head_b,
            float* __restrict__ z, float* __restrict__ z_mean,
            float* __restrict__ z_lv, float* __restrict__ x_mean)
{
    __shared__ float xs[2 * 512];
    __shared__ float h1s[2 * 304];
    __shared__ float h2s[2 * 304];
    __shared__ float zms[2 * 64];
    __shared__ float zvs[2 * 64];

    const int tid = threadIdx.x;

    if (blockIdx.x >= 128) {
        // ---- weight split + x_mean init ----
        int i = (blockIdx.x - 128) * 256 + tid;        // 0 .. 102399
        {
            int n = i / NHP, k = i % NHP;
            float v = (n < NH && k < NH) ? gen2_w[n * NH + k] : 0.f;
            float h, l; split_bf(v, h, l);
            g_g2w_hi[i] = __float2bfloat16(h);
            g_g2w_lo[i] = __float2bfloat16(l);
        }
        if (i < NHP * NL) {
            int n = i / NL, k = i % NL;
            float v = (n < NH) ? gen1_w[n * NL + k] : 0.f;
            float h, l; split_bf(v, h, l);
            g_g1w_hi[i] = __float2bfloat16(h);
            g_g1w_lo[i] = __float2bfloat16(l);
        }
        for (int j = i; j < MTOT; j += 400 * 256)
            x_mean[j] = head_b[j & 511];
        return;
    }

    // ---- encoder: 2 batch rows per CTA ----
    const int r0 = blockIdx.x * 2;

    for (int i = tid; i < 2 * 512; i += 256) {
        int r = i >> 9, k = i & 511;
        xs[i] = x[(r0 + r) * 512 + k];
    }
    __syncthreads();

    for (int n = tid; n < NH; n += 256) {
        float acc[2] = {0, 0};
        const float4* wp = reinterpret_cast<const float4*>(w1 + n * 512);
        for (int kq = 0; kq < 128; kq++) {
            float4 w = wp[kq];
#pragma unroll
            for (int r = 0; r < 2; r++) {
                float4 xv = *reinterpret_cast<const float4*>(&xs[r * 512 + kq * 4]);
                acc[r] += w.x * xv.x + w.y * xv.y + w.z * xv.z + w.w * xv.w;
            }
        }
        float bb = b1[n];
#pragma unroll
        for (int r = 0; r < 2; r++) h1s[r * 304 + n] = fmaxf(acc[r] + bb, 0.f);
    }
    __syncthreads();

    for (int n = tid; n < NH; n += 256) {
        float acc[2] = {0, 0};
        const float4* wp = reinterpret_cast<const float4*>(w2 + n * 300);
        for (int kq = 0; kq < 75; kq++) {
            float4 w = wp[kq];
#pragma unroll
            for (int r = 0; r < 2; r++) {
                float4 hv = *reinterpret_cast<const float4*>(&h1s[r * 304 + kq * 4]);
                acc[r] += w.x * hv.x + w.y * hv.y + w.z * hv.z + w.w * hv.w;
            }
        }
        float bb = b2[n];
#pragma unroll
        for (int r = 0; r < 2; r++) h2s[r * 304 + n] = fmaxf(acc[r] + bb, 0.f);
    }
    __syncthreads();

    if (tid < 128) {
        int n = tid & 63;
        const float* wrow = (tid < 64) ? (zmw + n * 300) : (zvw + n * 300);
        float bb = (tid < 64) ? zmb[n] : zvb[n];
        float acc[2] = {0, 0};
        const float4* wp = reinterpret_cast<const float4*>(wrow);
        for (int kq = 0; kq < 75; kq++) {
            float4 w = wp[kq];
#pragma unroll
            for (int r = 0; r < 2; r++) {
                float4 hv = *reinterpret_cast<const float4*>(&h2s[r * 304 + kq * 4]);
                acc[r] += w.x * hv.x + w.y * hv.y + w.z * hv.z + w.w * hv.w;
            }
        }
#pragma unroll
        for (int r = 0; r < 2; r++) {
            float v = acc[r] + bb;
            int m = r0 + r;
            if (tid < 64) { zms[r * 64 + n] = v; z_mean[m * 64 + n] = v; }
            else          { zvs[r * 64 + n] = v; z_lv[m * 64 + n] = v; }
        }
    }
    __syncthreads();

    if (tid < 64) {
        int n = tid;
#pragma unroll
        for (int r = 0; r < 2; r++) {
            int m = r0 + r;
            z[m * 64 + n] = zms[r * 64 + n] + eps[m * 64 + n] * expf(0.5f * zvs[r * 64 + n]);
        }
    }
}

// ---------------------------------------------------------------------------
// Fused decoder: one CTA = 64 rows (one b, 64 consecutive d).
//   Phase 1: g1 = relu((z[b].*W[d]) @ gen1_w^T)  -> split bf16 in SMEM A-region
//   Phase 2: g2 = relu(g1 @ gen2_w^T + b); x_mean = g2 . head_w[d] + head_b[d]
// grid = 2048, 512 threads, 16 warps = 2 rowgroups(32r = 2 m-tiles)
//                                     x 8 n-splits(40n = 5 n-tiles).
// acc[2][5][4] = 40 regs. Dead padding (n>=304, K>=304) skipped.
// SMEM ~191 KB: A hi/lo [64][328] + overlaid scratch + bias.
// ---------------------------------------------------------------------------
static constexpr uint32_t A_HI  = 0;                         // 64*656 = 41984
static constexpr uint32_t A_LO  = 41984;
static constexpr uint32_t SCR   = 83968;
// phase-1 overlay of SCR:
static constexpr uint32_t P1_ZH  = SCR;                      // 64*144  = 9216
static constexpr uint32_t P1_ZL  = SCR + 9216;
static constexpr uint32_t P1_WH  = SCR + 18432;              // 320*144 = 46080
static constexpr uint32_t P1_WL  = SCR + 64512;              // end SCR+110592
// phase-2 overlay of SCR: B chunks [2 bufs][320*80] hi/lo
static constexpr uint32_t P2_BH  = SCR;                      // + buf*25600
static constexpr uint32_t P2_BL  = SCR + 51200;              // + buf*25600
static constexpr uint32_t GB_OFF = SCR + 110592;             // 304 floats
static constexpr uint32_t FUSED_SMEM = GB_OFF + 1216;        // 195776

__global__ void __launch_bounds__(512, 1)
decoder_kernel(const float* __restrict__ z, const float* __restrict__ W,
               const float* __restrict__ gen2_b,
               const float* __restrict__ head_w,
               const float* __restrict__ head_b,
               float* __restrict__ x_mean)
{
    extern __shared__ char sm[];
    const uint32_t sb = smem_u32(sm);
    float* g2bs = reinterpret_cast<float*>(sm + GB_OFF);
    const int tid  = threadIdx.x;
    const int wid  = tid >> 5;
    const int lane = tid & 31;
    const int g = lane >> 2, c = lane & 3;

    const int m0 = blockIdx.x * 64;
    const int b  = m0 >> 9;
    const int d0 = m0 & 511;

    const int rg = wid >> 3;          // rowgroup: local rows rg*32 .. +31 (2 mt)
    const int ns = wid & 7;           // n split: [ns*40, +40) = 5 n-tiles
    const int mrow0 = rg * 32;
    const int nbase = ns * 40;
    const bool live3 = (ns != 7);     // ns==7: tiles j=3 (304-311), j=4 (312-319) dead

    // per-lane ldmatrix offsets
    const uint32_t x4p1 = (uint32_t)((lane & 15) * PITCH  + ((lane >> 4) << 4));
    const uint32_t x2p1 = (uint32_t)((lane & 7) * PITCH  + (((lane >> 3) & 1) << 4));
    const uint32_t x4pA = (uint32_t)((lane & 15) * PITCHA + ((lane >> 4) << 4));
    const uint32_t x4p2 = (uint32_t)((lane & 15) * PITCH2 + ((lane >> 4) << 4));
    const uint32_t x2p2 = (uint32_t)((lane & 7) * PITCH2 + (((lane >> 3) & 1) << 4));

    // ---- prologue staging: bias, masked z (split), gen1_w (split) ----
    for (int i = tid; i < 304; i += 512)
        g2bs[i] = (i < 300) ? gen2_b[i] : 0.f;

    for (int idx = tid; idx < 64 * 16; idx += 512) {
        int r = idx >> 4, lq = idx & 15;
        float4 wv = *reinterpret_cast<const float4*>(&W[(d0 + r) * 64 + lq * 4]);
        float4 zv = *reinterpret_cast<const float4*>(&z[b * 64 + lq * 4]);
        float v0 = wv.x * zv.x, v1 = wv.y * zv.y, v2 = wv.z * zv.z, v3 = wv.w * zv.w;
        float h0, l0, h1, l1, h2, l2, h3, l3;
        split_bf(v0, h0, l0); split_bf(v1, h1, l1);
        split_bf(v2, h2, l2); split_bf(v3, h3, l3);
        uint2 hi2 = make_uint2(pack2bf(h0, h1), pack2bf(h2, h3));
        uint2 lo2 = make_uint2(pack2bf(l0, l1), pack2bf(l2, l3));
        uint32_t off = (uint32_t)(r * PITCH + lq * 8);
        *reinterpret_cast<uint2*>(sm + P1_ZH + off) = hi2;
        *reinterpret_cast<uint2*>(sm + P1_ZL + off) = lo2;
    }
    {
        const uint4* wh = reinterpret_cast<const uint4*>(g_g1w_hi);
        const uint4* wl = reinterpret_cast<const uint4*>(g_g1w_lo);
        for (int idx = tid; idx < 320 * 8; idx += 512) {
            int n = idx >> 3, kq = idx & 7;
            uint32_t off = (uint32_t)(n * PITCH + kq * 16);
            *reinterpret_cast<uint4*>(sm + P1_WH + off) = wh[idx];
            *reinterpret_cast<uint4*>(sm + P1_WL + off) = wl[idx];
        }
    }
    __syncthreads();

    float acc[2][5][4];
#pragma unroll
    for (int mi = 0; mi < 2; mi++)
#pragma unroll
        for (int j = 0; j < 5; j++)
#pragma unroll
            for (int e = 0; e < 4; e++) acc[mi][j][e] = 0.f;

    // ---- phase 1 mainloop: K = 64 ----
#pragma unroll
    for (int kt = 0; kt < 4; kt++) {
        uint32_t Ah[2][4], Al[2][4];
#pragma unroll
        for (int mi = 0; mi < 2; mi++) {
            uint32_t base = (uint32_t)((mrow0 + mi * 16) * PITCH + kt * 32) + x4p1;
            ldsm_x4(Ah[mi], sb + P1_ZH + base);
            ldsm_x4(Al[mi], sb + P1_ZL + base);
        }
        // pair 0: n-tiles 0,1
        {
            uint32_t bbad = (uint32_t)(nbase * PITCH + kt * 32) + x4p1;
            uint32_t bhi[4], blo[4];
            ldsm_x4(bhi, sb + P1_WH + bbad);
            ldsm_x4(blo, sb + P1_WL + bbad);
#pragma unroll
            for (int mi = 0; mi < 2; mi++) {
                mma16816(acc[mi][0], Ah[mi], bhi[0], bhi[2]);
                mma16816(acc[mi][1], Ah[mi], bhi[1], bhi[3]);
            }
#pragma unroll
            for (int mi = 0; mi < 2; mi++) {
                mma16816(acc[mi][0], Al[mi], bhi[0], bhi[2]);
                mma16816(acc[mi][1], Al[mi], bhi[1], bhi[3]);
            }
#pragma unroll
            for (int mi = 0; mi < 2; mi++) {
                mma16816(acc[mi][0], Ah[mi], blo[0], blo[2]);
                mma16816(acc[mi][1], Ah[mi], blo[1], blo[3]);
            }
        }
        // pair 1: n-tiles 2,3 (3 dead for ns==7)
        {
            uint32_t bbad = (uint32_t)((nbase + 16) * PITCH + kt * 32) + x4p1;
            uint32_t bhi[4], blo[4];
            ldsm_x4(bhi, sb + P1_WH + bbad);
            ldsm_x4(blo, sb + P1_WL + bbad);
#pragma unroll
            for (int mi = 0; mi < 2; mi++) {
                mma16816(acc[mi][2], Ah[mi], bhi[0], bhi[2]);
                if (live3) mma16816(acc[mi][3], Ah[mi], bhi[1], bhi[3]);
            }
#pragma unroll
            for (int mi = 0; mi < 2; mi++) {
                mma16816(acc[mi][2], Al[mi], bhi[0], bhi[2]);
                if (live3) mma16816(acc[mi][3], Al[mi], bhi[1], bhi[3]);
            }
#pragma unroll
            for (int mi = 0; mi < 2; mi++) {
                mma16816(acc[mi][2], Ah[mi], blo[0], blo[2]);
                if (live3) mma16816(acc[mi][3], Ah[mi], blo[1], blo[3]);
            }
        }
        // single: n-tile 4 (dead for ns==7)
        if (live3) {
            uint32_t bbad = (uint32_t)((nbase + 32) * PITCH + kt * 32) + x2p1;
            uint32_t bhi2[2], blo2[2];
            ldsm_x2(bhi2, sb + P1_WH + bbad);
            ldsm_x2(blo2, sb + P1_WL + bbad);
#pragma unroll
            for (int mi = 0; mi < 2; mi++)
                mma16816(acc[mi][4], Ah[mi], bhi2[0], bhi2[1]);
#pragma unroll
            for (int mi = 0; mi < 2; mi++)
                mma16816(acc[mi][4], Al[mi], bhi2[0], bhi2[1]);
#pragma unroll
            for (int mi = 0; mi < 2; mi++)
                mma16816(acc[mi][4], Ah[mi], blo2[0], blo2[1]);
        }
    }

    // ---- phase 1 epilogue: relu + split -> SMEM A region ----
#pragma unroll
    for (int mi = 0; mi < 2; mi++) {
        const int r0 = mrow0 + mi * 16 + g;   // local rows
        const int r1 = r0 + 8;
#pragma unroll
        for (int j = 0; j < 5; j++) {
            const int n0 = nbase + j * 8 + 2 * c;
            float h0f, l0f, h1f, l1f, h2f, l2f, h3f, l3f;
            split_bf(fmaxf(acc[mi][j][0], 0.f), h0f, l0f);
            split_bf(fmaxf(acc[mi][j][1], 0.f), h1f, l1f);
            split_bf(fmaxf(acc[mi][j][2], 0.f), h2f, l2f);
            split_bf(fmaxf(acc[mi][j][3], 0.f), h3f, l3f);
            uint32_t o0 = (uint32_t)(r0 * PITCHA + n0 * 2);
            uint32_t o1 = (uint32_t)(r1 * PITCHA + n0 * 2);
            *reinterpret_cast<uint32_t*>(sm + A_HI + o0) = pack2bf(h0f, h1f);
            *reinterpret_cast<uint32_t*>(sm + A_LO + o0) = pack2bf(l0f, l1f);
            *reinterpret_cast<uint32_t*>(sm + A_HI + o1) = pack2bf(h2f, h3f);
            *reinterpret_cast<uint32_t*>(sm + A_LO + o1) = pack2bf(l2f, l3f);
        }
    }
    __syncthreads();   // gen1_w reads + A writes done; scratch now free for B

    // ---- phase 2: K = 320 in 10 cp.async K32 chunks, 1 barrier per chunk ----
    const uint4* bhg = reinterpret_cast<const uint4*>(g_g2w_hi);
    const uint4* blg = reinterpret_cast<const uint4*>(g_g2w_lo);

    auto stage = [&](int kc, int buf) {
        uint32_t bh = sb + P2_BH + buf * 25600;
        uint32_t bl = sb + P2_BL + buf * 25600;
        for (int e = tid; e < 2560; e += 512) {
            int idx = e % 1280;
            int r = idx >> 2, kq = idx & 3;
            uint32_t off = (uint32_t)(r * PITCH2 + kq * 16);
            size_t gi = (size_t)r * 40 + kc * 4 + kq;
            if (e < 1280) cpasync16(bh + off, bhg + gi);
            else          cpasync16(bl + off, blg + gi);
        }
    };

#pragma unroll
    for (int mi = 0; mi < 2; mi++)
#pragma unroll
        for (int j = 0; j < 5; j++)
#pragma unroll
            for (int e = 0; e < 4; e++) acc[mi][j][e] = 0.f;

    stage(0, 0); CP_COMMIT();
    stage(1, 1); CP_COMMIT();
    CP_WAIT(1); __syncthreads();     // chunk 0 ready

#pragma unroll 1
    for (int kc = 0; kc < 10; kc++) {
        const int buf = kc & 1;
        uint32_t bh = sb + P2_BH + buf * 25600;
        uint32_t bl = sb + P2_BL + buf * 25600;

#pragma unroll
        for (int kt = 0; kt < 2; kt++) {
            if (kc == 9 && kt == 1) break;   // K 304..319 is all zeros — skip
            uint32_t Ah[2][4], Al[2][4];
#pragma unroll
            for (int mi = 0; mi < 2; mi++) {
                uint32_t abase = (uint32_t)((mrow0 + mi * 16) * PITCHA
                                            + kc * 64 + kt * 32) + x4pA;
                ldsm_x4(Ah[mi], sb + A_HI + abase);
                ldsm_x4(Al[mi], sb + A_LO + abase);
            }
            // pair 0: n-tiles 0,1
            {
                uint32_t bbad = (uint32_t)(nbase * PITCH2 + kt * 32) + x4p2;
                uint32_t bhi[4], blo[4];
                ldsm_x4(bhi, bh + bbad);
                ldsm_x4(blo, bl + bbad);
#pragma unroll
                for (int mi = 0; mi < 2; mi++) {
                    mma16816(acc[mi][0], Ah[mi], bhi[0], bhi[2]);
                    mma16816(acc[mi][1], Ah[mi], bhi[1], bhi[3]);
                }
#pragma unroll
                for (int mi = 0; mi < 2; mi++) {
                    mma16816(acc[mi][0], Al[mi], bhi[0], bhi[2]);
                    mma16816(acc[mi][1], Al[mi], bhi[1], bhi[3]);
                }
#pragma unroll
                for (int mi = 0; mi < 2; mi++) {
                    mma16816(acc[mi][0], Ah[mi], blo[0], blo[2]);
                    mma16816(acc[mi][1], Ah[mi], blo[1], blo[3]);
                }
            }
            // pair 1: n-tiles 2,3 (3 dead for ns==7)
            {
                uint32_t bbad = (uint32_t)((nbase + 16) * PITCH2 + kt * 32) + x4p2;
                uint32_t bhi[4], blo[4];
                ldsm_x4(bhi, bh + bbad);
                ldsm_x4(blo, bl + bbad);
#pragma unroll
                for (int mi = 0; mi < 2; mi++) {
                    mma16816(acc[mi][2], Ah[mi], bhi[0], bhi[2]);
                    if (live3) mma16816(acc[mi][3], Ah[mi], bhi[1], bhi[3]);
                }
#pragma unroll
                for (int mi = 0; mi < 2; mi++) {
                    mma16816(acc[mi][2], Al[mi], bhi[0], bhi[2]);
                    if (live3) mma16816(acc[mi][3], Al[mi], bhi[1], bhi[3]);
                }
#pragma unroll
                for (int mi = 0; mi < 2; mi++) {
                    mma16816(acc[mi][2], Ah[mi], blo[0], blo[2]);
                    if (live3) mma16816(acc[mi][3], Ah[mi], blo[1], blo[3]);
                }
            }
            // single: n-tile 4 (dead for ns==7)
            if (live3) {
                uint32_t bbad = (uint32_t)((nbase + 32) * PITCH2 + kt * 32) + x2p2;
                uint32_t bhi2[2], blo2[2];
                ldsm_x2(bhi2, bh + bbad);
                ldsm_x2(blo2, bl + bbad);
#pragma unroll
                for (int mi = 0; mi < 2; mi++)
                    mma16816(acc[mi][4], Ah[mi], bhi2[0], bhi2[1]);
#pragma unroll
                for (int mi = 0; mi < 2; mi++)
                    mma16816(acc[mi][4], Al[mi], bhi2[0], bhi2[1]);
#pragma unroll
                for (int mi = 0; mi < 2; mi++)
                    mma16816(acc[mi][4], Ah[mi], blo2[0], blo2[1]);
            }
        }

        if (kc < 9) {
            CP_WAIT(0);          // chunk kc+1 landed while we computed kc
            __syncthreads();     // publish kc+1; buf kc now free for restage
            if (kc < 8) { stage(kc + 2, buf); CP_COMMIT(); }
        }
    }

    // ---- epilogue: relu + bias, dot with head_w, quad-reduce, accumulate ----
#pragma unroll
    for (int mi = 0; mi < 2; mi++) {
        const int r0 = m0 + mrow0 + mi * 16 + g;
        const int r1 = r0 + 8;
        const float* hw0 = head_w + (size_t)(r0 & 511) * 300;
        const float* hw1 = head_w + (size_t)(r1 & 511) * 300;
        float x0 = 0.f, x1 = 0.f;
#pragma unroll
        for (int j = 0; j < 5; j++) {
            const int n0 = nbase + j * 8 + 2 * c;
            if (n0 < 300) {
                float bb = g2bs[n0];
                float v0 = fmaxf(acc[mi][j][0] + bb, 0.f);
                float v2 = fmaxf(acc[mi][j][2] + bb, 0.f);
                x0 = fmaf(v0, hw0[n0], x0);
                x1 = fmaf(v2, hw1[n0], x1);
            }
            if (n0 + 1 < 300) {
                float bb = g2bs[n0 + 1];
                float v1 = fmaxf(acc[mi][j][1] + bb, 0.f);
                float v3 = fmaxf(acc[mi][j][3] + bb, 0.f);
                x0 = fmaf(v1, hw0[n0 + 1], x0);
                x1 = fmaf(v3, hw1[n0 + 1], x1);
            }
        }
        x0 += __shfl_xor_sync(0xffffffffu, x0, 1);
        x0 += __shfl_xor_sync(0xffffffffu, x0, 2);
        x1 += __shfl_xor_sync(0xffffffffu, x1, 1);
        x1 += __shfl_xor_sync(0xffffffffu, x1, 2);
        if (c == 0) {
            atomicAdd(&x_mean[r0], x0);
            atomicAdd(&x_mean[r1], x1);
        }
    }
}

// ---------------------------------------------------------------------------
extern "C" void kernel_launch(void* const* d_in, const int* in_sizes, int n_in,
                              void* d_out, int out_size)
{
    const float* x      = (const float*)d_in[0];
    const float* eps    = (const float*)d_in[1];
    const float* W      = (const float*)d_in[2];
    const float* enc1_w = (const float*)d_in[3];
    const float* enc1_b = (const float*)d_in[4];
    const float* enc2_w = (const float*)d_in[5];
    const float* enc2_b = (const float*)d_in[6];
    const float* zm_w   = (const float*)d_in[7];
    const float* zm_b   = (const float*)d_in[8];
    const float* zv_w   = (const float*)d_in[9];
    const float* zv_b   = (const float*)d_in[10];
    const float* gen1_w = (const float*)d_in[11];
    const float* gen2_w = (const float*)d_in[12];
    const float* gen2_b = (const float*)d_in[13];
    const float* head_w = (const float*)d_in[14];
    const float* head_b = (const float*)d_in[15];

    float* out    = (float*)d_out;
    float* x_mean = out;                 // [256,512]
    float* zbuf   = out + NB * ND;       // [256,64]
    float* z_mean = zbuf + NB * NL;      // [256,64]
    float* z_lv   = z_mean + NB * NL;    // [256,64]

    cudaFuncSetAttribute(decoder_kernel,
                         cudaFuncAttributeMaxDynamicSharedMemorySize,
                         (int)FUSED_SMEM);

    prep_kernel<<<528, 256>>>(x, eps, enc1_w, enc1_b, enc2_w, enc2_b,
                              zm_w, zm_b, zv_w, zv_b, gen1_w, gen2_w, head_b,
                              zbuf, z_mean, z_lv, x_mean);
    decoder_kernel<<<MTOT / 64, 512, FUSED_SMEM>>>(zbuf, W, gen2_b,
                                                   head_w, head_b, x_mean);
}